// round 14
// baseline (speedup 1.0000x reference)
#include <cuda_runtime.h>
#include <cuda_bf16.h>
#include <cstdint>

#define DT2 1.0e-6f

// ---------------- device scratch (no allocations allowed) ----------------
__device__ float g_partial[8 * 4096 * 64];   // [ksplit][row*64+s]
__device__ float g_acc[4096 * 64];           // reduced: sum over ksplit (overwritten each launch)

static __device__ __forceinline__ uint32_t smem_u32(const void* p) {
    uint32_t a;
    asm("{ .reg .u64 t; cvta.to.shared.u64 t, %1; cvt.u32.u64 %0, t; }"
        : "=r"(a) : "l"(p));
    return a;
}

// ===================== kernel 1: tf32 mma.sync GEMM with cp.async pipeline =====================
// P[ksplit][row0:+128][0:64] = deno[row0:+128, k0:+512] @ X[k0:+512, 0:64]
// grid (32, 8) = 256 CTAs -> one full wave at 2 CTAs/SM (296 slots).
// 256 threads = 8 warps, warp grid 4(M) x 2(N), warp tile 32x32.
// Kc = 32 fp32 per chunk (16 chunks), 4-stage cp.async pipeline, raw fp32 -> tf32 mma.
//
// SMEM per stage: A [128 rows][32 fp32], row stride 144B (36 words; LDS conflict-free)
//                 B [32 k][64 fp32],     row stride 288B (72 words; conflict-free)
static constexpr uint32_t A_ST   = 144;
static constexpr uint32_t ABYTES = 128 * A_ST;            // 18432
static constexpr uint32_t B_ST   = 288;
static constexpr uint32_t BBYTES = 32 * B_ST;             // 9216
static constexpr uint32_t STAGE_SZ = ABYTES + BBYTES;     // 27648
static constexpr int STAGES = 4;
static constexpr uint32_t SMEM_REQ = STAGES * STAGE_SZ;   // 110592

static constexpr int KSPLIT = 8;
static constexpr int KPER = 4096 / KSPLIT;                // 512
static constexpr int KC = 32;
static constexpr int NCHUNK = KPER / KC;                  // 16

#define CP_ASYNC16(saddr, gptr) \
    asm volatile("cp.async.cg.shared.global [%0], [%1], 16;" \
                 :: "r"(saddr), "l"(gptr) : "memory")
#define CP_COMMIT() asm volatile("cp.async.commit_group;" ::: "memory")
#define CP_WAIT(N)  asm volatile("cp.async.wait_group %0;" :: "n"(N) : "memory")

static __device__ __forceinline__ void mma_tf32(
    float* c, uint32_t a0, uint32_t a1, uint32_t a2, uint32_t a3,
    uint32_t b0, uint32_t b1)
{
    asm volatile(
        "mma.sync.aligned.m16n8k8.row.col.f32.tf32.tf32.f32 "
        "{%0,%1,%2,%3}, {%4,%5,%6,%7}, {%8,%9}, {%0,%1,%2,%3};"
        : "+f"(c[0]), "+f"(c[1]), "+f"(c[2]), "+f"(c[3])
        : "r"(a0), "r"(a1), "r"(a2), "r"(a3), "r"(b0), "r"(b1));
}

__global__ __launch_bounds__(256) void ws_gemm_kernel(
    const float* __restrict__ deno, const float* __restrict__ X)
{
    extern __shared__ char sm[];
    const uint32_t smb = smem_u32(sm);

    const int tid = threadIdx.x;
    const int wid = tid >> 5;
    const int lid = tid & 31;
    const int wm = wid >> 1;          // 0..3 : warp M index
    const int wn = wid & 1;           // 0..1 : warp N index
    const int g = lid >> 2;           // group 0..7
    const int tig = lid & 3;          // thread-in-group

    const int row0 = blockIdx.x * 128;
    const int k0 = blockIdx.y * KPER;

    float acc[2][4][4];
#pragma unroll
    for (int i = 0; i < 2; i++)
#pragma unroll
        for (int j = 0; j < 4; j++)
#pragma unroll
            for (int q = 0; q < 4; q++) acc[i][j][q] = 0.0f;

    // staging lambda: issue one chunk's cp.async into stage buffer s
    auto issue_stage = [&](int s, int kc) {
        uint32_t Ab = smb + (uint32_t)s * STAGE_SZ;
        uint32_t Bb = Ab + ABYTES;
        // A: 128 rows x 8 x 16B = 1024 ops, 4 per thread
#pragma unroll
        for (int i = 0; i < 4; i++) {
            int o = i * 256 + tid;
            int r = o >> 3, seg = o & 7;
            CP_ASYNC16(Ab + (uint32_t)r * A_ST + (uint32_t)seg * 16,
                       deno + (size_t)(row0 + r) * 4096 + kc + seg * 4);
        }
        // B: 32 rows x 16 x 16B = 512 ops, 2 per thread
#pragma unroll
        for (int i = 0; i < 2; i++) {
            int o = i * 256 + tid;
            int r = o >> 4, seg = o & 15;
            CP_ASYNC16(Bb + (uint32_t)r * B_ST + (uint32_t)seg * 16,
                       X + (size_t)(kc + r) * 64 + seg * 4);
        }
    };

    // ---- prologue: issue stages 0,1,2 ----
    issue_stage(0, k0);          CP_COMMIT();
    issue_stage(1, k0 + KC);     CP_COMMIT();
    issue_stage(2, k0 + 2 * KC); CP_COMMIT();

    // fragment base offsets within a stage (bytes)
    const uint32_t a_base = (uint32_t)(wm * 32 + g) * A_ST + (uint32_t)tig * 4;
    const uint32_t b_base = ABYTES + (uint32_t)tig * B_ST + (uint32_t)(wn * 32 + g) * 4;

#pragma unroll 1
    for (int c = 0; c < NCHUNK; c++) {
        if (c < NCHUNK - 2)       { CP_WAIT(2); }
        else if (c == NCHUNK - 2) { CP_WAIT(1); }
        else                      { CP_WAIT(0); }
        __syncthreads();

        if (c + 3 < NCHUNK) {
            issue_stage((c + 3) & 3, k0 + (c + 3) * KC);
            CP_COMMIT();
        }

        const char* St = sm + (size_t)(c & 3) * STAGE_SZ;
#pragma unroll
        for (int ks = 0; ks < 4; ks++) {
            // A fragments: 2 m-frags x 4 regs
            uint32_t a[2][4];
#pragma unroll
            for (int mf = 0; mf < 2; mf++) {
                const char* ap = St + a_base + (uint32_t)mf * (16 * A_ST) + (uint32_t)ks * 32;
                a[mf][0] = *reinterpret_cast<const uint32_t*>(ap);
                a[mf][1] = *reinterpret_cast<const uint32_t*>(ap + 8 * A_ST);
                a[mf][2] = *reinterpret_cast<const uint32_t*>(ap + 16);
                a[mf][3] = *reinterpret_cast<const uint32_t*>(ap + 8 * A_ST + 16);
            }
#pragma unroll
            for (int nf = 0; nf < 4; nf++) {
                const char* bp = St + b_base + (uint32_t)ks * (8 * B_ST) + (uint32_t)nf * 32;
                uint32_t b0 = *reinterpret_cast<const uint32_t*>(bp);
                uint32_t b1 = *reinterpret_cast<const uint32_t*>(bp + 4 * B_ST);
                mma_tf32(acc[0][nf], a[0][0], a[0][1], a[0][2], a[0][3], b0, b1);
                mma_tf32(acc[1][nf], a[1][0], a[1][1], a[1][2], a[1][3], b0, b1);
            }
        }
    }

    // ---- epilogue: plain coalesced STG of partials (no atomics) ----
    float* Pp = g_partial + (size_t)blockIdx.y * (4096 * 64);
#pragma unroll
    for (int mf = 0; mf < 2; mf++) {
#pragma unroll
        for (int nf = 0; nf < 4; nf++) {
            int row = row0 + wm * 32 + mf * 16 + g;
            int col = wn * 32 + nf * 8 + tig * 2;
            float2 v0 = make_float2(acc[mf][nf][0], acc[mf][nf][1]);
            float2 v1 = make_float2(acc[mf][nf][2], acc[mf][nf][3]);
            *reinterpret_cast<float2*>(Pp + (size_t)row * 64 + col) = v0;
            *reinterpret_cast<float2*>(Pp + (size_t)(row + 8) * 64 + col) = v1;
        }
    }
}

// ===================== kernel 1b: reduce 8 partials -> g_acc (overwrite) =====================
__global__ __launch_bounds__(256) void ws_reduce_kernel()
{
    int f4 = blockIdx.x * 256 + threadIdx.x;   // 0 .. 65535 float4 slots
    float4 t = *reinterpret_cast<const float4*>(g_partial + (size_t)f4 * 4);
#pragma unroll
    for (int p = 1; p < 8; p++) {
        float4 v = *reinterpret_cast<const float4*>(
            g_partial + (size_t)p * 262144 + (size_t)f4 * 4);
        t.x += v.x; t.y += v.y; t.z += v.z; t.w += v.w;
    }
    *reinterpret_cast<float4*>(g_acc + (size_t)f4 * 4) = t;
}

// ===================== kernel 2: fused out = Y + dt^2 * scatter(acc) =====================
__global__ __launch_bounds__(256) void ws_copy_kernel(
    const float* __restrict__ Y, const int* __restrict__ xidx,
    float* __restrict__ out)
{
    __shared__ int fast_s;
    __shared__ unsigned char inv_s[4096];

    const int tid = threadIdx.x;
    const size_t base = (size_t)blockIdx.x * 4096;   // float4 index of first elem

    if (tid == 0) fast_s = 1;
    __syncthreads();
    if (tid < 64) {
        if (__ldg(xidx + tid) != tid * 64) fast_s = 0;
    }
    __syncthreads();

    if (fast_s) {
        const bool adder = (tid & 15) == 0;
#pragma unroll
        for (int half = 0; half < 2; half++) {
            float4 v[8];
#pragma unroll
            for (int i = 0; i < 8; i++) {
                size_t idx = base + (half * 8 + i) * 256 + tid;
                v[i] = __ldcs(reinterpret_cast<const float4*>(Y) + idx);
            }
            if (adder) {
#pragma unroll
                for (int i = 0; i < 8; i++) {
                    size_t idx = base + (half * 8 + i) * 256 + tid;
                    int row = (int)(idx >> 10);
                    int s = (int)((idx & 1023) >> 4);
                    v[i].x += DT2 * g_acc[row * 64 + s];
                }
            }
#pragma unroll
            for (int i = 0; i < 8; i++) {
                size_t idx = base + (half * 8 + i) * 256 + tid;
                __stcs(reinterpret_cast<float4*>(out) + idx, v[i]);
            }
        }
    } else {
        // general fallback: per-element inverse-table lookup
        reinterpret_cast<int4*>(inv_s)[tid] = make_int4(0, 0, 0, 0);
        __syncthreads();
        if (tid < 64) inv_s[__ldg(xidx + tid)] = (unsigned char)(tid + 1);
        __syncthreads();
#pragma unroll
        for (int it = 0; it < 16; it++) {
            size_t idx = base + it * 256 + tid;
            int row = (int)(idx >> 10);
            int c4 = (int)(idx & 1023);
            float4 v = __ldcs(reinterpret_cast<const float4*>(Y) + idx);
            uchar4 u = *reinterpret_cast<const uchar4*>(&inv_s[c4 * 4]);
            if (u.x | u.y | u.z | u.w) {
                int rb = row * 64;
                if (u.x) v.x += DT2 * g_acc[rb + u.x - 1];
                if (u.y) v.y += DT2 * g_acc[rb + u.y - 1];
                if (u.z) v.z += DT2 * g_acc[rb + u.z - 1];
                if (u.w) v.w += DT2 * g_acc[rb + u.w - 1];
            }
            __stcs(reinterpret_cast<float4*>(out) + idx, v);
        }
    }
}

// ===================== launch =====================
extern "C" void kernel_launch(void* const* d_in, const int* in_sizes, int n_in,
                              void* d_out, int out_size)
{
    const float* Y    = (const float*)d_in[0];
    const float* X    = (const float*)d_in[1];
    const float* deno = (const float*)d_in[2];
    const int*   xi   = (const int*)d_in[3];
    float* out = (float*)d_out;

    cudaFuncSetAttribute(ws_gemm_kernel,
                         cudaFuncAttributeMaxDynamicSharedMemorySize, SMEM_REQ);

    ws_gemm_kernel<<<dim3(32, KSPLIT), 256, SMEM_REQ>>>(deno, X);
    ws_reduce_kernel<<<256, 256>>>();
    ws_copy_kernel<<<1024, 256>>>(Y, xi, out);
}